// round 2
// baseline (speedup 1.0000x reference)
#include <cuda_runtime.h>
#include <cuda_fp16.h>
#include <cstdint>
#include <cstddef>

// ---------------------------------------------------------------------------
// FFB encoder fused kernel (round 1): 3-term compensated f16 mma.sync GEMMs
//   x@W = xh@Wh_ + xl@Wh_ + xh@Wl_   (both operands exact to ~2^-22)
//   x = sin(5(x@Ws+bs)) + grid_sin ; out += sin(10(x@Wh+bh)), 6 levels
// ---------------------------------------------------------------------------

#define TM      64            // points per CTA
#define XH      264           // half stride of activation rows (132 words == 4 mod 32: conflict free)
#define WST     136           // half stride of W slab rows (68 words == 4 mod 32: conflict free)
#define WBUFH   34816         // halfs per W slab buffer (256 rows x 136)
#define SM_XSH  0
#define SM_XSL  33792
#define SM_WBUF 67584
#define SM_GSM  206848
#define SM_ASM  209920
#define SM_PSM  222208
#define SMEM_TOTAL 222976

// [l][n][0:256]   = half(scale*W[l][k][n])            (hi)
// [l][n][256:512] = half(scale*W[l][k][n] - hi)       (lo)
__device__ __align__(16) __half g_WsT[6 * 256 * 512];
__device__ __align__(16) __half g_WhT[6 * 256 * 512];

// range-reduced sin: full __sinf accuracy for args up to ~1e3
__device__ __forceinline__ float sinr(float x) {
    float k = rintf(x * 0.15915494309189535f);
    float r = fmaf(k, -6.2831855f, x);
    r = fmaf(k, 1.7484555e-7f, r);
    return __sinf(r);
}

__global__ void prep_kernel(const float* __restrict__ Ws, const float* __restrict__ Wh) {
    int idx = blockIdx.x * 256 + threadIdx.x;
    if (idx < 6 * 256 * 256) {
        int l = idx >> 16, rem = idx & 65535, n = rem >> 8, k = rem & 255;
        int src = (l << 16) + (k << 8) + n;   // transpose [k][n] -> [n][k]
        int dst = (l << 17) + (n << 9) + k;
        float ws = 5.0f  * Ws[src];
        float wh = 10.0f * Wh[src];
        __half wsh = __float2half_rn(ws);
        __half whh = __float2half_rn(wh);
        g_WsT[dst]       = wsh;
        g_WsT[dst + 256] = __float2half_rn(ws - __half2float(wsh));
        g_WhT[dst]       = whh;
        g_WhT[dst + 256] = __float2half_rn(wh - __half2float(whh));
    }
}

__device__ __forceinline__ void mma16816(float* c, const unsigned* a, unsigned b0, unsigned b1) {
    asm volatile(
        "mma.sync.aligned.m16n8k16.row.col.f32.f16.f16.f32 "
        "{%0,%1,%2,%3}, {%4,%5,%6,%7}, {%8,%9}, {%0,%1,%2,%3};\n"
        : "+f"(c[0]), "+f"(c[1]), "+f"(c[2]), "+f"(c[3])
        : "r"(a[0]), "r"(a[1]), "r"(a[2]), "r"(a[3]), "r"(b0), "r"(b1));
}

__device__ __forceinline__ void cpasync16(__half* dst, const __half* src) {
    unsigned d = (unsigned)__cvta_generic_to_shared(dst);
    asm volatile("cp.async.ca.shared.global [%0], [%1], 16;\n" :: "r"(d), "l"(src));
}
template <int NN> __device__ __forceinline__ void cpwait() {
    asm volatile("cp.async.wait_group %0;\n" :: "n"(NN));
}

// C[64,256] += x @ W^T with 3-term compensation.
// W source layout: [n][512] = 256 hi-k then 256 lo-k halfs.
// Slab buffer row: [64 hi | 64 lo | 8 pad] halfs.
__device__ __forceinline__ void do_gemm(float (&c)[2][8][4],
                                        const __half* __restrict__ Wg, __half* wbufs,
                                        const __half* xsh, const __half* xsl,
                                        int rm, int cn, int g, int tg, int tid) {
    {   // prologue: slab 0 (hi 128B + lo 128B per row)
        const __half* srch = Wg + tid * 512;
        const __half* srcl = srch + 256;
        __half* dst = wbufs + tid * WST;
        #pragma unroll
        for (int j = 0; j < 8; j++) cpasync16(dst + j * 8, srch + j * 8);
        #pragma unroll
        for (int j = 0; j < 8; j++) cpasync16(dst + 64 + j * 8, srcl + j * 8);
        asm volatile("cp.async.commit_group;\n");
    }
    #pragma unroll
    for (int s = 0; s < 4; s++) {
        if (s < 3) {
            const __half* srch = Wg + tid * 512 + (s + 1) * 64;
            const __half* srcl = srch + 256;
            __half* dst = wbufs + ((s + 1) & 1) * WBUFH + tid * WST;
            #pragma unroll
            for (int j = 0; j < 8; j++) cpasync16(dst + j * 8, srch + j * 8);
            #pragma unroll
            for (int j = 0; j < 8; j++) cpasync16(dst + 64 + j * 8, srcl + j * 8);
            asm volatile("cp.async.commit_group;\n");
            cpwait<1>();
        } else {
            cpwait<0>();
        }
        __syncthreads();
        const __half* wb = wbufs + (s & 1) * WBUFH;
        #pragma unroll
        for (int kt = 0; kt < 4; kt++) {
            const int k = s * 64 + kt * 16;
            const int kk = kt * 16;
            unsigned ah[2][4], al[2][4];
            #pragma unroll
            for (int mt = 0; mt < 2; mt++) {
                const __half* ph0 = xsh + (rm + mt * 16 + g) * XH + k + 2 * tg;
                const __half* ph1 = ph0 + 8 * XH;
                ah[mt][0] = *(const unsigned*)(ph0);
                ah[mt][1] = *(const unsigned*)(ph1);
                ah[mt][2] = *(const unsigned*)(ph0 + 8);
                ah[mt][3] = *(const unsigned*)(ph1 + 8);
                const __half* pl0 = xsl + (rm + mt * 16 + g) * XH + k + 2 * tg;
                const __half* pl1 = pl0 + 8 * XH;
                al[mt][0] = *(const unsigned*)(pl0);
                al[mt][1] = *(const unsigned*)(pl1);
                al[mt][2] = *(const unsigned*)(pl0 + 8);
                al[mt][3] = *(const unsigned*)(pl1 + 8);
            }
            #pragma unroll
            for (int nt = 0; nt < 8; nt++) {
                const __half* pb = wb + (cn + nt * 8 + g) * WST + kk + 2 * tg;
                unsigned bh0 = *(const unsigned*)(pb);
                unsigned bh1 = *(const unsigned*)(pb + 8);
                unsigned bl0 = *(const unsigned*)(pb + 64);
                unsigned bl1 = *(const unsigned*)(pb + 72);
                mma16816(c[0][nt], ah[0], bh0, bh1);
                mma16816(c[1][nt], ah[1], bh0, bh1);
                mma16816(c[0][nt], al[0], bh0, bh1);
                mma16816(c[1][nt], al[1], bh0, bh1);
                mma16816(c[0][nt], ah[0], bl0, bl1);
                mma16816(c[1][nt], ah[1], bl0, bl1);
            }
        }
        __syncthreads();
    }
}

__global__ void __launch_bounds__(256, 1) ffb_kernel(
    const float* __restrict__ in_pos, const float* __restrict__ table,
    const float* __restrict__ ffn_A, const float* __restrict__ W0,
    const float* __restrict__ b0v, const float* __restrict__ bsv,
    const float* __restrict__ bhv, float* __restrict__ out) {
    extern __shared__ char smem[];
    __half* xsh   = (__half*)(smem + SM_XSH);
    __half* xsl   = (__half*)(smem + SM_XSL);
    __half* wbufs = (__half*)(smem + SM_WBUF);
    float*  gsm   = (float*)(smem + SM_GSM);   // [6][64][2] trilinear features
    float*  Asm   = (float*)(smem + SM_ASM);   // [6][2][256] 2*pi*sigma*ffn_A
    float*  psm   = (float*)(smem + SM_PSM);   // [64][3] positions

    const int tid = threadIdx.x;
    const int lane = tid & 31, warp = tid >> 5;
    const int g = lane >> 2, tg = lane & 3;
    const int wm = warp >> 2, wn = warp & 3;
    const int rm = wm * 32, cn = wn * 64;
    const int row0 = blockIdx.x * TM;

    for (int i = tid; i < TM * 3; i += 256) psm[i] = in_pos[row0 * 3 + i];
    for (int i = tid; i < 3072; i += 256) {
        int l = i >> 9;
        Asm[i] = 6.283185307179586f * (5.0f * (float)(1 << l)) * ffn_A[i];
    }
    __syncthreads();

    // ---- multires hash grid (matches reference f32 math) ----
    for (int t = tid; t < TM * 6; t += 256) {
        int l = t >> 6;
        int p = t & 63;
        float res = 16.0f * (float)(1 << l);
        float px = (psm[p * 3 + 0] + 1.0f) * 0.5f * res;
        float py = (psm[p * 3 + 1] + 1.0f) * 0.5f * res;
        float pz = (psm[p * 3 + 2] + 1.0f) * 0.5f * res;
        float fx = floorf(px), fy = floorf(py), fz = floorf(pz);
        float frx = px - fx, fry = py - fy, frz = pz - fz;
        int ix = (int)fx, iy = (int)fy, iz = (int)fz;
        float g0 = 0.f, g1 = 0.f;
        const float* tb = table + (size_t)l * (524288 * 2);
        #pragma unroll
        for (int cc = 0; cc < 8; cc++) {
            int ox = (cc >> 2) & 1, oy = (cc >> 1) & 1, oz = cc & 1;
            unsigned h = ((unsigned)(ix + ox))
                       ^ ((unsigned)(iy + oy) * 2654435761u)
                       ^ ((unsigned)(iz + oz) * 805459861u);
            h &= 524287u;
            float2 f2 = *(const float2*)(tb + (size_t)h * 2);
            float w = (ox ? frx : 1.0f - frx) * (oy ? fry : 1.0f - fry) * (oz ? frz : 1.0f - frz);
            g0 = fmaf(w, f2.x, g0);
            g1 = fmaf(w, f2.y, g1);
        }
        gsm[t * 2] = g0; gsm[t * 2 + 1] = g1;
    }

    // ---- layer 0: x = sin(5*(pos @ W0 + b0)) ----
    {
        int n = tid;
        float w0a = 5.0f * W0[n], w0b = 5.0f * W0[256 + n], w0c = 5.0f * W0[512 + n];
        float bb = 5.0f * b0v[n];
        for (int p = 0; p < TM; p++) {
            float x = fmaf(psm[p * 3 + 2], w0c, fmaf(psm[p * 3 + 1], w0b, fmaf(psm[p * 3], w0a, bb)));
            float sv = sinr(x);
            __half h = __float2half_rn(sv);
            xsh[p * XH + n] = h;
            xsl[p * XH + n] = __float2half_rn(sv - __half2float(h));
        }
    }
    __syncthreads();

    float acc[2][8][4];
    #pragma unroll
    for (int mt = 0; mt < 2; mt++)
        #pragma unroll
        for (int nt = 0; nt < 8; nt++)
            #pragma unroll
            for (int e = 0; e < 4; e++) acc[mt][nt][e] = 0.f;

    for (int lev = 0; lev < 6; lev++) {
        // ---- GEMM1: c = xs @ (5*Ws)^T + 5*bs ----
        float c[2][8][4];
        #pragma unroll
        for (int nt = 0; nt < 8; nt++) {
            float2 bv = *(const float2*)(bsv + lev * 256 + cn + nt * 8 + 2 * tg);
            float bx = 5.0f * bv.x, by = 5.0f * bv.y;
            c[0][nt][0] = bx; c[0][nt][1] = by; c[0][nt][2] = bx; c[0][nt][3] = by;
            c[1][nt][0] = bx; c[1][nt][1] = by; c[1][nt][2] = bx; c[1][nt][3] = by;
        }
        do_gemm(c, g_WsT + lev * 131072, wbufs, xsh, xsl, rm, cn, g, tg, tid);

        // ---- x = sin(c) + sin(grid proj); write back hi/lo ----
        float2 gx[4];
        #pragma unroll
        for (int rr = 0; rr < 4; rr++) {
            int r = rm + (rr >> 1) * 16 + (rr & 1) * 8 + g;
            gx[rr] = *(const float2*)(gsm + (lev * 64 + r) * 2);
        }
        #pragma unroll
        for (int nt = 0; nt < 8; nt++) {
            int n0 = cn + nt * 8 + 2 * tg;
            float2 a0 = *(const float2*)(Asm + lev * 512 + n0);
            float2 a1 = *(const float2*)(Asm + lev * 512 + 256 + n0);
            #pragma unroll
            for (int mt = 0; mt < 2; mt++) {
                float2 gA = gx[mt * 2], gB = gx[mt * 2 + 1];
                float x0 = sinr(c[mt][nt][0]) + sinr(gA.x * a0.x + gA.y * a1.x);
                float x1 = sinr(c[mt][nt][1]) + sinr(gA.x * a0.y + gA.y * a1.y);
                float x2 = sinr(c[mt][nt][2]) + sinr(gB.x * a0.x + gB.y * a1.x);
                float x3 = sinr(c[mt][nt][3]) + sinr(gB.x * a0.y + gB.y * a1.y);
                int r0 = rm + mt * 16 + g;
                __half h0 = __float2half_rn(x0), h1 = __float2half_rn(x1);
                __half h2 = __float2half_rn(x2), h3 = __float2half_rn(x3);
                *(__half2*)(xsh + r0 * XH + n0)       = __halves2half2(h0, h1);
                *(__half2*)(xsh + (r0 + 8) * XH + n0) = __halves2half2(h2, h3);
                *(__half2*)(xsl + r0 * XH + n0) =
                    __halves2half2(__float2half_rn(x0 - __half2float(h0)),
                                   __float2half_rn(x1 - __half2float(h1)));
                *(__half2*)(xsl + (r0 + 8) * XH + n0) =
                    __halves2half2(__float2half_rn(x2 - __half2float(h2)),
                                   __float2half_rn(x3 - __half2float(h3)));
            }
        }
        __syncthreads();

        // ---- GEMM2: c2 = xs @ (10*Wh)^T + 10*bh; out += sin(c2) ----
        float c2[2][8][4];
        #pragma unroll
        for (int nt = 0; nt < 8; nt++) {
            float2 bv = *(const float2*)(bhv + lev * 256 + cn + nt * 8 + 2 * tg);
            float bx = 10.0f * bv.x, by = 10.0f * bv.y;
            c2[0][nt][0] = bx; c2[0][nt][1] = by; c2[0][nt][2] = bx; c2[0][nt][3] = by;
            c2[1][nt][0] = bx; c2[1][nt][1] = by; c2[1][nt][2] = bx; c2[1][nt][3] = by;
        }
        do_gemm(c2, g_WhT + lev * 131072, wbufs, xsh, xsl, rm, cn, g, tg, tid);
        #pragma unroll
        for (int mt = 0; mt < 2; mt++)
            #pragma unroll
            for (int nt = 0; nt < 8; nt++)
                #pragma unroll
                for (int e = 0; e < 4; e++) acc[mt][nt][e] += sinr(c2[mt][nt][e]);
    }

    // ---- store out [N,256] f32 ----
    #pragma unroll
    for (int mt = 0; mt < 2; mt++)
        #pragma unroll
        for (int nt = 0; nt < 8; nt++) {
            int r = row0 + rm + mt * 16 + g;
            int n0 = cn + nt * 8 + 2 * tg;
            *(float2*)(out + (size_t)r * 256 + n0) = make_float2(acc[mt][nt][0], acc[mt][nt][1]);
            *(float2*)(out + (size_t)(r + 8) * 256 + n0) = make_float2(acc[mt][nt][2], acc[mt][nt][3]);
        }
}

extern "C" void kernel_launch(void* const* d_in, const int* in_sizes, int n_in,
                              void* d_out, int out_size) {
    (void)in_sizes; (void)n_in; (void)out_size;
    const float* in_pos = (const float*)d_in[0];
    const float* table  = (const float*)d_in[1];
    const float* ffn_A  = (const float*)d_in[2];
    const float* W0     = (const float*)d_in[3];
    const float* b0     = (const float*)d_in[4];
    const float* Ws     = (const float*)d_in[5];
    const float* bs     = (const float*)d_in[6];
    const float* Wh     = (const float*)d_in[7];
    const float* bh     = (const float*)d_in[8];
    float* out = (float*)d_out;

    cudaFuncSetAttribute(ffb_kernel, cudaFuncAttributeMaxDynamicSharedMemorySize, SMEM_TOTAL);

    prep_kernel<<<1536, 256>>>(Ws, Wh);
    ffb_kernel<<<262144 / TM, 256, SMEM_TOTAL>>>(in_pos, table, ffn_A, W0, b0, bs, bh, out);
}

// round 8
// speedup vs baseline: 1.5797x; 1.5797x over previous
#include <cuda_runtime.h>
#include <cuda_fp16.h>
#include <cstdint>
#include <cstddef>

// ---------------------------------------------------------------------------
// FFB encoder (round 6): mma.sync f16 3-term compensated GEMMs, ldmatrix
// fragment loads, 512 threads (16 warps), cp.async.cg K=32 W slabs.
//   x@W = xh@Whi + xl@Whi + xh@Wlo
// ---------------------------------------------------------------------------

#define TM    64             // points per CTA
#define XH    264            // half stride of activation rows (528B: LDSM conflict-free)
#define WROW  40             // halfs per W slab row (80B: LDSM conflict-free)
#define WPART 10240          // halfs per part in one slab buffer (256*40)
#define WBUFH 20480          // halfs per slab buffer (2 parts)

// ---- SMEM byte offsets ----
#define SM_XSH  0            // 33792
#define SM_XSL  33792        // 33792
#define SM_WBUF 67584        // 81920 (2 buffers x 20480 halfs)
#define SM_GSM  149504       // 3072:  [6][64][2] f32 grid feats
#define SM_ASM  152576       // 12288: [6][2][256] f32
#define SM_BSM  164864       // 6144:  5*bs
#define SM_BHM  171008       // 6144:  10*bh
#define SM_PSM  177152       // 768:   [64][3]
#define SM_W0M  177920       // 4096:  scaled W0/b0
#define SMEM_TOTAL 182016

// W planes: [l][part(hi=0,lo=1)][n][k] halfs
__device__ __align__(16) __half g_WsT[6 * 2 * 256 * 256];
__device__ __align__(16) __half g_WhT[6 * 2 * 256 * 256];

__device__ __forceinline__ unsigned smem_u32(const void* p) {
    unsigned a;
    asm("{ .reg .u64 t; cvta.to.shared.u64 t, %1; cvt.u32.u64 %0, t; }" : "=r"(a) : "l"(p));
    return a;
}

// range-reduced sin: full __sinf accuracy for |x| up to ~1e3
__device__ __forceinline__ float sinr(float x) {
    float k = rintf(x * 0.15915494309189535f);
    float r = fmaf(k, -6.2831855f, x);
    r = fmaf(k, 1.7484555e-7f, r);
    return __sinf(r);
}

__global__ void prep_kernel(const float* __restrict__ Ws, const float* __restrict__ Wh) {
    int idx = blockIdx.x * 256 + threadIdx.x;
    if (idx < 6 * 256 * 256) {
        int l = idx >> 16, rem = idx & 65535, n = rem >> 8, k = rem & 255;
        int src = (l << 16) + (k << 8) + n;             // transpose [k][n] -> [n][k]
        int dhi = ((l * 2 + 0) * 256 + n) * 256 + k;
        int dlo = ((l * 2 + 1) * 256 + n) * 256 + k;
        float ws = 5.0f * Ws[src];
        float wh = 10.0f * Wh[src];
        __half wsh = __float2half_rn(ws);
        __half whh = __float2half_rn(wh);
        g_WsT[dhi] = wsh; g_WsT[dlo] = __float2half_rn(ws - __half2float(wsh));
        g_WhT[dhi] = whh; g_WhT[dlo] = __float2half_rn(wh - __half2float(whh));
    }
}

__device__ __forceinline__ void mma16816(float* c, const unsigned* a, unsigned b0, unsigned b1) {
    asm volatile(
        "mma.sync.aligned.m16n8k16.row.col.f32.f16.f16.f32 "
        "{%0,%1,%2,%3}, {%4,%5,%6,%7}, {%8,%9}, {%0,%1,%2,%3};\n"
        : "+f"(c[0]), "+f"(c[1]), "+f"(c[2]), "+f"(c[3])
        : "r"(a[0]), "r"(a[1]), "r"(a[2]), "r"(a[3]), "r"(b0), "r"(b1));
}

#define LDSM_X4(r0, r1, r2, r3, addr) \
    asm volatile("ldmatrix.sync.aligned.m8n8.x4.shared.b16 {%0,%1,%2,%3}, [%4];" \
        : "=r"(r0), "=r"(r1), "=r"(r2), "=r"(r3) : "r"(addr))

__device__ __forceinline__ void cpasync16cg(unsigned dst, const void* src) {
    asm volatile("cp.async.cg.shared.global [%0], [%1], 16;\n" :: "r"(dst), "l"(src));
}
template <int NN> __device__ __forceinline__ void cpwait() {
    asm volatile("cp.async.wait_group %0;\n" :: "n"(NN));
}

// fill one K=32 slab (both hi/lo parts) into buffer at smem byte addr bufb
__device__ __forceinline__ void fill_slab(const __half* __restrict__ plane, int s,
                                          unsigned bufb, int tid) {
    #pragma unroll
    for (int it = 0; it < 4; it++) {
        int c = tid + it * 512;              // 0..2047
        int part = c >> 10, n = (c >> 2) & 255, j = c & 3;
        const __half* src = plane + ((size_t)((part << 8) + n)) * 256 + s * 32 + j * 8;
        unsigned dst = bufb + (unsigned)(part * WPART + n * WROW + j * 8) * 2;
        cpasync16cg(dst, src);
    }
    asm volatile("cp.async.commit_group;\n");
}

// C[64,256] += x @ W^T with 3-term compensation. 16 warps: 4m x 4n.
__device__ __forceinline__ void do_gemm(float (&c)[8][4],
                                        const __half* __restrict__ plane,
                                        unsigned sbase, unsigned aoffB,
                                        unsigned boffrow, unsigned bcol, int tid) {
    fill_slab(plane, 0, sbase + SM_WBUF, tid);
    #pragma unroll 1
    for (int s = 0; s < 8; s++) {
        if (s < 7) {
            fill_slab(plane, s + 1, sbase + SM_WBUF + (unsigned)(((s + 1) & 1) * WBUFH) * 2, tid);
            cpwait<1>();
        } else {
            cpwait<0>();
        }
        __syncthreads();
        unsigned wb = sbase + SM_WBUF + (unsigned)((s & 1) * WBUFH) * 2;
        #pragma unroll
        for (int t = 0; t < 2; t++) {
            int kabs = s * 32 + t * 16;
            unsigned ah[4], al[4];
            LDSM_X4(ah[0], ah[1], ah[2], ah[3], sbase + SM_XSH + aoffB + (unsigned)kabs * 2);
            LDSM_X4(al[0], al[1], al[2], al[3], sbase + SM_XSL + aoffB + (unsigned)kabs * 2);
            unsigned b[8][2];
            // --- hi part of W ---
            #pragma unroll
            for (int ntp = 0; ntp < 4; ntp++) {
                unsigned r0, r1, r2, r3;
                LDSM_X4(r0, r1, r2, r3,
                        wb + (unsigned)((boffrow + ntp * 16) * WROW + bcol + t * 16) * 2);
                b[2 * ntp][0] = r0; b[2 * ntp][1] = r1;
                b[2 * ntp + 1][0] = r2; b[2 * ntp + 1][1] = r3;
            }
            #pragma unroll
            for (int nt = 0; nt < 8; nt++) {
                mma16816(c[nt], ah, b[nt][0], b[nt][1]);
                mma16816(c[nt], al, b[nt][0], b[nt][1]);
            }
            // --- lo part of W ---
            #pragma unroll
            for (int ntp = 0; ntp < 4; ntp++) {
                unsigned r0, r1, r2, r3;
                LDSM_X4(r0, r1, r2, r3,
                        wb + (unsigned)(WPART + (boffrow + ntp * 16) * WROW + bcol + t * 16) * 2);
                b[2 * ntp][0] = r0; b[2 * ntp][1] = r1;
                b[2 * ntp + 1][0] = r2; b[2 * ntp + 1][1] = r3;
            }
            #pragma unroll
            for (int nt = 0; nt < 8; nt++)
                mma16816(c[nt], ah, b[nt][0], b[nt][1]);
        }
        __syncthreads();
    }
}

__global__ void __launch_bounds__(512, 1) ffb_kernel(
    const float* __restrict__ in_pos, const float* __restrict__ table,
    const float* __restrict__ ffn_A, const float* __restrict__ W0,
    const float* __restrict__ b0v, const float* __restrict__ bsv,
    const float* __restrict__ bhv, float* __restrict__ out) {
    extern __shared__ char smem[];
    const unsigned sbase = smem_u32(smem);
    __half* xsh = (__half*)(smem + SM_XSH);
    __half* xsl = (__half*)(smem + SM_XSL);
    float* gsm = (float*)(smem + SM_GSM);
    float* Asm = (float*)(smem + SM_ASM);
    float* bsm = (float*)(smem + SM_BSM);
    float* bhm = (float*)(smem + SM_BHM);
    float* psm = (float*)(smem + SM_PSM);
    float* w0m = (float*)(smem + SM_W0M);

    const int tid = threadIdx.x;
    const int lane = tid & 31, wid = tid >> 5;
    const int g = lane >> 2, tg = lane & 3;
    const int wm = wid >> 2, wn = wid & 3;        // 4m x 4n warps
    const int rm = wm * 16, cn = wn * 64;
    const int row0 = blockIdx.x * TM;

    // ldmatrix address components (byte offsets)
    const unsigned aoffB = (unsigned)((rm + (lane & 15)) * XH + ((lane >> 4) << 3)) * 2;
    const unsigned boffrow = (unsigned)(cn + (lane & 7) + ((lane >> 4) << 3));
    const unsigned bcol = (unsigned)(((lane >> 3) & 1) << 3);

    // ---- prologue staging ----
    for (int i = tid; i < TM * 3; i += 512) psm[i] = in_pos[row0 * 3 + i];
    for (int i = tid; i < 6 * 256; i += 512) {
        bsm[i] = 5.0f * bsv[i];
        bhm[i] = 10.0f * bhv[i];
    }
    for (int i = tid; i < 6 * 512; i += 512) {
        int l = i >> 9;
        Asm[i] = 6.283185307179586f * (5.0f * (float)(1 << l)) * ffn_A[i];
    }
    if (tid < 256) {
        w0m[tid] = 5.0f * W0[tid];
        w0m[256 + tid] = 5.0f * W0[256 + tid];
        w0m[512 + tid] = 5.0f * W0[512 + tid];
        w0m[768 + tid] = 5.0f * b0v[tid];
    }
    __syncthreads();

    // ---- multires hash grid (f32 math matches reference) ----
    if (tid < TM * 6) {
        int t = tid;
        int l = t >> 6;
        int p = t & 63;
        float res = 16.0f * (float)(1 << l);
        float px = (psm[p * 3 + 0] + 1.0f) * 0.5f * res;
        float py = (psm[p * 3 + 1] + 1.0f) * 0.5f * res;
        float pz = (psm[p * 3 + 2] + 1.0f) * 0.5f * res;
        float fx = floorf(px), fy = floorf(py), fz = floorf(pz);
        float frx = px - fx, fry = py - fy, frz = pz - fz;
        int ix = (int)fx, iy = (int)fy, iz = (int)fz;
        float g0 = 0.f, g1 = 0.f;
        const float* tb = table + (size_t)l * (524288 * 2);
        #pragma unroll
        for (int cc = 0; cc < 8; cc++) {
            int ox = (cc >> 2) & 1, oy = (cc >> 1) & 1, oz = cc & 1;
            unsigned h = ((unsigned)(ix + ox))
                       ^ ((unsigned)(iy + oy) * 2654435761u)
                       ^ ((unsigned)(iz + oz) * 805459861u);
            h &= 524287u;
            float2 f2 = *(const float2*)(tb + (size_t)h * 2);
            float w = (ox ? frx : 1.0f - frx) * (oy ? fry : 1.0f - fry) * (oz ? frz : 1.0f - frz);
            g0 = fmaf(w, f2.x, g0);
            g1 = fmaf(w, f2.y, g1);
        }
        gsm[t * 2] = g0; gsm[t * 2 + 1] = g1;
    }

    // ---- layer 0: x = sin(5*(pos @ W0 + b0)) -> hi/lo in smem ----
    for (int i = tid; i < TM * 256; i += 512) {
        int p = i >> 8, n = i & 255;
        float x = fmaf(psm[p * 3 + 2], w0m[512 + n],
                  fmaf(psm[p * 3 + 1], w0m[256 + n],
                  fmaf(psm[p * 3], w0m[n], w0m[768 + n])));
        float sv = sinr(x);
        __half h = __float2half_rn(sv);
        xsh[p * XH + n] = h;
        xsl[p * XH + n] = __float2half_rn(sv - __half2float(h));
    }
    __syncthreads();

    float acc[8][4];
    #pragma unroll
    for (int nt = 0; nt < 8; nt++)
        #pragma unroll
        for (int e = 0; e < 4; e++) acc[nt][e] = 0.f;

    for (int lev = 0; lev < 6; lev++) {
        // ---- GEMM1: c = xs @ (5*Ws)^T + 5*bs ----
        float c[8][4];
        #pragma unroll
        for (int nt = 0; nt < 8; nt++) {
            float2 bv = *(const float2*)(bsm + lev * 256 + cn + nt * 8 + 2 * tg);
            c[nt][0] = bv.x; c[nt][1] = bv.y; c[nt][2] = bv.x; c[nt][3] = bv.y;
        }
        do_gemm(c, g_WsT + (size_t)lev * 131072, sbase, aoffB, boffrow, bcol, tid);

        // ---- epilogue 1: x = sin(c) + sin(grid proj); write back hi/lo ----
        {
            int r0 = rm + g;
            float2 gA = *(const float2*)(gsm + (lev * 64 + r0) * 2);
            float2 gB = *(const float2*)(gsm + (lev * 64 + r0 + 8) * 2);
            #pragma unroll
            for (int nt = 0; nt < 8; nt++) {
                int n0 = cn + nt * 8 + 2 * tg;
                float2 a0 = *(const float2*)(Asm + lev * 512 + n0);
                float2 a1 = *(const float2*)(Asm + lev * 512 + 256 + n0);
                float x0 = sinr(c[nt][0]) + sinr(fmaf(gA.y, a1.x, gA.x * a0.x));
                float x1 = sinr(c[nt][1]) + sinr(fmaf(gA.y, a1.y, gA.x * a0.y));
                float x2 = sinr(c[nt][2]) + sinr(fmaf(gB.y, a1.x, gB.x * a0.x));
                float x3 = sinr(c[nt][3]) + sinr(fmaf(gB.y, a1.y, gB.x * a0.y));
                __half h0 = __float2half_rn(x0), h1 = __float2half_rn(x1);
                __half h2 = __float2half_rn(x2), h3 = __float2half_rn(x3);
                *(__half2*)(xsh + r0 * XH + n0)       = __halves2half2(h0, h1);
                *(__half2*)(xsh + (r0 + 8) * XH + n0) = __halves2half2(h2, h3);
                *(__half2*)(xsl + r0 * XH + n0) =
                    __halves2half2(__float2half_rn(x0 - __half2float(h0)),
                                   __float2half_rn(x1 - __half2float(h1)));
                *(__half2*)(xsl + (r0 + 8) * XH + n0) =
                    __halves2half2(__float2half_rn(x2 - __half2float(h2)),
                                   __float2half_rn(x3 - __half2float(h3)));
            }
        }
        __syncthreads();

        // ---- GEMM2: c2 = xs @ (10*Wh)^T + 10*bh; out += sin(c2) ----
        float c2[8][4];
        #pragma unroll
        for (int nt = 0; nt < 8; nt++) {
            float2 bv = *(const float2*)(bhm + lev * 256 + cn + nt * 8 + 2 * tg);
            c2[nt][0] = bv.x; c2[nt][1] = bv.y; c2[nt][2] = bv.x; c2[nt][3] = bv.y;
        }
        do_gemm(c2, g_WhT + (size_t)lev * 131072, sbase, aoffB, boffrow, bcol, tid);
        #pragma unroll
        for (int nt = 0; nt < 8; nt++)
            #pragma unroll
            for (int e = 0; e < 4; e++) acc[nt][e] += sinr(c2[nt][e]);
        // (no barrier needed: next GEMM1 begins with fill into the buffer last
        //  read two slabs ago; the final __syncthreads inside do_gemm covers it)
    }

    // ---- store out [N,256] f32 ----
    #pragma unroll
    for (int nt = 0; nt < 8; nt++) {
        int r = row0 + rm + g;
        int n0 = cn + nt * 8 + 2 * tg;
        *(float2*)(out + (size_t)r * 256 + n0) = make_float2(acc[nt][0], acc[nt][1]);
        *(float2*)(out + (size_t)(r + 8) * 256 + n0) = make_float2(acc[nt][2], acc[nt][3]);
    }
}

extern "C" void kernel_launch(void* const* d_in, const int* in_sizes, int n_in,
                              void* d_out, int out_size) {
    (void)in_sizes; (void)n_in; (void)out_size;
    const float* in_pos = (const float*)d_in[0];
    const float* table  = (const float*)d_in[1];
    const float* ffn_A  = (const float*)d_in[2];
    const float* W0     = (const float*)d_in[3];
    const float* b0     = (const float*)d_in[4];
    const float* Ws     = (const float*)d_in[5];
    const float* bs     = (const float*)d_in[6];
    const float* Wh     = (const float*)d_in[7];
    const float* bh     = (const float*)d_in[8];
    float* out = (float*)d_out;

    cudaFuncSetAttribute(ffb_kernel, cudaFuncAttributeMaxDynamicSharedMemorySize, SMEM_TOTAL);

    prep_kernel<<<1536, 256>>>(Ws, Wh);
    ffb_kernel<<<262144 / TM, 512, SMEM_TOTAL>>>(in_pos, table, ffn_A, W0, b0, bs, bh, out);
}